// round 6
// baseline (speedup 1.0000x reference)
#include <cuda_runtime.h>
#include <math.h>

#define N_G   1024
#define SCALE 1.0f
#define DXC   (2.0f / 31.0f)
#define QCUT  60.0f                // dropped terms < e^-30 of dominant: negligible
#define GPB   32                   // gaussians per block in net kernel
#define CANDCAP 512

__device__ float d_img[N_G * 75];  // (N, 3, 5, 5): c*25 + kx*5 + ky

__device__ __forceinline__ float tanha(float x) {
    float y;
    asm("tanh.approx.f32 %0, %1;" : "=f"(y) : "f"(x));
    return y;
}

// ---------------------------------------------------------------------------
// Kernel 1: sampling with per-block candidate list.
// 200 blocks x 128 threads; block = 128 consecutive samples (~5 gaussians).
// ---------------------------------------------------------------------------
__global__ void __launch_bounds__(128) k_samples(
    const float* __restrict__ means, const float* __restrict__ u,
    const float* __restrict__ scaling, const float* __restrict__ transform)
{
    __shared__ float4 cA[CANDCAP];   // mx, my, r2max, u
    __shared__ float4 cB[CANDCAP];   // a, b, c, trace
    __shared__ int    s_wcnt[4], s_wbase[4], s_total;
    __shared__ float  s_bb[4];
    __shared__ float  s_red[4][4];

    const int tid = threadIdx.x;
    if (tid == 0) s_total = 0;

    const int s  = blockIdx.x * 128 + tid;
    const int i  = s / 25;
    const int k  = s % 25;
    const int kx = k / 5;
    const int ky = k % 5;
    const float sx = means[2 * i]     + (float)(kx - 2) * DXC;
    const float sy = means[2 * i + 1] + (float)(ky - 2) * DXC;

    // block bbox of sample positions
    float mnx = sx, mxx = sx, mny = sy, mxy = sy;
    #pragma unroll
    for (int o = 16; o > 0; o >>= 1) {
        mnx = fminf(mnx, __shfl_xor_sync(0xffffffffu, mnx, o));
        mxx = fmaxf(mxx, __shfl_xor_sync(0xffffffffu, mxx, o));
        mny = fminf(mny, __shfl_xor_sync(0xffffffffu, mny, o));
        mxy = fmaxf(mxy, __shfl_xor_sync(0xffffffffu, mxy, o));
    }
    if ((tid & 31) == 0) {
        s_red[tid >> 5][0] = mnx; s_red[tid >> 5][1] = mxx;
        s_red[tid >> 5][2] = mny; s_red[tid >> 5][3] = mxy;
    }
    __syncthreads();
    if (tid == 0) {
        float a0 = s_red[0][0], a1 = s_red[0][1], a2 = s_red[0][2], a3 = s_red[0][3];
        for (int w2 = 1; w2 < 4; ++w2) {
            a0 = fminf(a0, s_red[w2][0]); a1 = fmaxf(a1, s_red[w2][1]);
            a2 = fminf(a2, s_red[w2][2]); a3 = fmaxf(a3, s_red[w2][3]);
        }
        s_bb[0] = a0; s_bb[1] = a1; s_bb[2] = a2; s_bb[3] = a3;
    }
    __syncthreads();
    const float bminx = s_bb[0], bmaxx = s_bb[1], bminy = s_bb[2], bmaxy = s_bb[3];

    // candidate scan + deterministic compaction (conics computed inline)
    const int wid = tid >> 5, lane = tid & 31;
    for (int c = 0; c < N_G / 128; ++c) {
        int j = c * 128 + tid;
        float mx = means[2 * j], my = means[2 * j + 1];
        float s0 = scaling[2 * j], s1 = scaling[2 * j + 1], t = transform[j];
        float A = s0 * s0, B = s0 * t, C = t * t + s1 * s1;
        float inv = 1.0f / (A * C - B * B);
        float ca =  C * inv, cb = -B * inv, cc = A * inv;
        float h = 0.5f * (A + C);
        float r = sqrtf(0.25f * (A - C) * (A - C) + B * B);
        float r2max = QCUT * (h + r);
        float ddx = fmaxf(fmaxf(bminx - mx, mx - bmaxx), 0.0f);
        float ddy = fmaxf(fmaxf(bminy - my, my - bmaxy), 0.0f);
        bool pred = (ddx * ddx + ddy * ddy) <= r2max;
        unsigned bm = __ballot_sync(0xffffffffu, pred);
        if (lane == 0) s_wcnt[wid] = __popc(bm);
        __syncthreads();
        if (tid == 0) {
            int acc = s_total;
            for (int w2 = 0; w2 < 4; ++w2) { s_wbase[w2] = acc; acc += s_wcnt[w2]; }
            s_total = acc;
        }
        __syncthreads();
        if (pred) {
            int idx = s_wbase[wid] + __popc(bm & ((1u << lane) - 1u));
            if (idx < CANDCAP) {
                cA[idx] = make_float4(mx, my, r2max, u[j]);
                cB[idx] = make_float4(ca, cb, cc, ca + cc);
            }
        }
        __syncthreads();
    }
    int cnt = s_total;
    if (cnt > CANDCAP) cnt = CANDCAP;

    // branchless evaluation over candidates
    float us = 0.0f, pd = 0.0f;
    for (int t2 = 0; t2 < cnt; ++t2) {
        float4 A  = cA[t2];
        float4 Bv = cB[t2];
        float dx = sx - A.x;
        float dy = sy - A.y;
        float Cd0 = Bv.x * dx + Bv.y * dy;
        float Cd1 = Bv.y * dx + Bv.z * dy;
        float q   = dx * Cd0 + dy * Cd1;
        float w   = __expf(-0.5f * q) * A.w;
        us += w;
        pd += w * (Cd0 * Cd0 + Cd1 * Cd1 - Bv.w);
    }
    float maskv = (fabsf(sx) < SCALE && fabsf(sy) < SCALE) ? 1.0f : 0.0f;
    d_img[i * 75 +  0 + k] = us;
    d_img[i * 75 + 25 + k] = pd;
    d_img[i * 75 + 50 + k] = maskv;
}

// ---------------------------------------------------------------------------
// Kernel 2: 4 stacked networks. GPB=32, 512 threads, grid (4,32) = 128 blocks.
// Weights loaded once per block and amortized over 32 gaussians (~74KB smem).
// All region offsets are multiples of 4 floats (16B) for LDS.128 alignment.
// ---------------------------------------------------------------------------
#define OFF_SWC   0        // 3750
#define OFF_SWE   3752     // 180
#define OFF_SWL   3932     // 6400  (16B aligned; row stride 80 keeps alignment)
#define OFF_SBC   10332    // 50
#define OFF_SBE   10384    // 30
#define OFF_SBL   10416    // 80
#define OFF_SHW   10496    // 160
#define OFF_SHB   10656    // 2
#define OFF_SPRM  10660    // 288
#define OFF_IMGT  10948    // 2400  (16B aligned; stride 32)
#define OFF_SHT   13348    // 2560  (16B aligned; stride 32)
#define OFF_SH2T  15908    // 2560  (16B aligned; stride 32)
#define OFF_HP    18468    // 256
#define SMEM_FLTS 18724

__global__ void __launch_bounds__(512) k_net(
    const float* __restrict__ conv_w, const float* __restrict__ conv_b,
    const float* __restrict__ emb_w,  const float* __restrict__ emb_b,
    const float* __restrict__ lin1_w, const float* __restrict__ lin1_b,
    const float* __restrict__ sol_w,  const float* __restrict__ sol_b,
    const float* __restrict__ tr_w,   const float* __restrict__ tr_b,
    const float* __restrict__ sc_w,   const float* __restrict__ sc_b,
    const float* __restrict__ tf_w,   const float* __restrict__ tf_b,
    const float* __restrict__ means,  const float* __restrict__ u,
    const float* __restrict__ scaling,const float* __restrict__ transform,
    float* __restrict__ out)
{
    extern __shared__ float sm[];
    float* swc  = sm + OFF_SWC;
    float* swe  = sm + OFF_SWE;
    float* swl  = sm + OFF_SWL;
    float* sbc  = sm + OFF_SBC;
    float* sbe  = sm + OFF_SBE;
    float* sbl  = sm + OFF_SBL;
    float* shw  = sm + OFF_SHW;
    float* shb  = sm + OFF_SHB;
    float* sprm = sm + OFF_SPRM;
    float* imgT = sm + OFF_IMGT;
    float* shT  = sm + OFF_SHT;
    float* sh2T = sm + OFF_SH2T;
    float* hpart= sm + OFF_HP;

    const int m   = blockIdx.x;
    const int g0  = blockIdx.y * GPB;
    const int tid = threadIdx.x;
    const int od  = (m == 1 || m == 2) ? 2 : 1;

    // ---- loads (once per block, 32 gaussians amortized) ----
    for (int idx = tid; idx < 3750; idx += 512) swc[idx] = conv_w[m * 3750 + idx];
    for (int idx = tid; idx < 180;  idx += 512) swe[idx] = emb_w[m * 180 + idx];
    for (int idx = tid; idx < 6400; idx += 512) swl[idx] = lin1_w[m * 6400 + idx];
    if (tid < 50) sbc[tid] = conv_b[m * 50 + tid];
    if (tid >= 64 && tid < 94)  sbe[tid - 64] = emb_b[m * 30 + (tid - 64)];
    if (tid >= 96 && tid < 176) sbl[tid - 96] = lin1_b[m * 80 + (tid - 96)];
    const float* hw; const float* hb;
    if      (m == 0) { hw = sol_w; hb = sol_b; }
    else if (m == 1) { hw = tr_w;  hb = tr_b;  }
    else if (m == 2) { hw = sc_w;  hb = sc_b;  }
    else             { hw = tf_w;  hb = tf_b;  }
    if (tid >= 192 && tid < 192 + 80 * 2 && tid - 192 < 80 * od) shw[tid - 192] = hw[tid - 192];
    if (tid < od) shb[tid] = hb[tid];
    if (tid >= 384 && tid < 384 + GPB) {
        int g = tid - 384, i = g0 + g;
        sprm[g * 9 + 0] = means[2 * i];
        sprm[g * 9 + 1] = means[2 * i + 1];
        sprm[g * 9 + 2] = u[i];
        sprm[g * 9 + 3] = scaling[2 * i];
        sprm[g * 9 + 4] = scaling[2 * i + 1];
        sprm[g * 9 + 5] = transform[i];
    }
    for (int idx = tid; idx < GPB * 75; idx += 512) {
        int g = idx / 75, kk = idx - g * 75;
        imgT[kk * 32 + g] = d_img[(g0 + g) * 75 + kk];
    }
    __syncthreads();

    // ---- stage 1: conv (tid<200: 2o x 4g) + emb (tid 256..495: 1q x 4g) ----
    if (tid < 200) {
        int ogrp = tid >> 3;            // 0..24
        int gb   = (tid & 7) * 4;       // 0..28
        int o0   = ogrp * 2;
        float b0 = sbc[o0], b1 = sbc[o0 + 1];
        float acc0[4] = {b0, b0, b0, b0};
        float acc1[4] = {b1, b1, b1, b1};
        const float* w0r = &swc[o0 * 75];
        const float* w1r = &swc[(o0 + 1) * 75];
        #pragma unroll 5
        for (int kk = 0; kk < 75; ++kk) {
            float w0 = w0r[kk], w1 = w1r[kk];
            float4 v = *(const float4*)&imgT[kk * 32 + gb];
            acc0[0] = fmaf(w0, v.x, acc0[0]); acc1[0] = fmaf(w1, v.x, acc1[0]);
            acc0[1] = fmaf(w0, v.y, acc0[1]); acc1[1] = fmaf(w1, v.y, acc1[1]);
            acc0[2] = fmaf(w0, v.z, acc0[2]); acc1[2] = fmaf(w1, v.z, acc1[2]);
            acc0[3] = fmaf(w0, v.w, acc0[3]); acc1[3] = fmaf(w1, v.w, acc1[3]);
        }
        #pragma unroll
        for (int b = 0; b < 4; ++b) {
            shT[o0 * 32 + gb + b]       = tanha(acc0[b]);
            shT[(o0 + 1) * 32 + gb + b] = tanha(acc1[b]);
        }
    } else if (tid >= 256 && tid < 496) {
        int et = tid - 256;
        int q  = et >> 3;               // 0..29
        int gb = (et & 7) * 4;          // 0..28
        float be = sbe[q];
        float acc[4] = {be, be, be, be};
        #pragma unroll
        for (int p = 0; p < 6; ++p) {
            float w = swe[p * 30 + q];
            acc[0] = fmaf(sprm[(gb + 0) * 9 + p], w, acc[0]);
            acc[1] = fmaf(sprm[(gb + 1) * 9 + p], w, acc[1]);
            acc[2] = fmaf(sprm[(gb + 2) * 9 + p], w, acc[2]);
            acc[3] = fmaf(sprm[(gb + 3) * 9 + p], w, acc[3]);
        }
        #pragma unroll
        for (int b = 0; b < 4; ++b) shT[(50 + q) * 32 + gb + b] = tanha(acc[b]);
    }
    __syncthreads();

    // ---- stage 2: 80x80, 4q x 2g tiles = 320 tasks ----
    if (tid < 320) {
        int q0 = (tid >> 4) * 4;        // 0..76
        int gb = (tid & 15) * 2;        // 0..30
        float acc[4][2];
        #pragma unroll
        for (int a = 0; a < 4; ++a) { acc[a][0] = sbl[q0 + a]; acc[a][1] = sbl[q0 + a]; }
        #pragma unroll 4
        for (int p = 0; p < 80; ++p) {
            float4 wv = *(const float4*)&swl[p * 80 + q0];
            float2 hv = *(const float2*)&shT[p * 32 + gb];
            acc[0][0] = fmaf(wv.x, hv.x, acc[0][0]); acc[0][1] = fmaf(wv.x, hv.y, acc[0][1]);
            acc[1][0] = fmaf(wv.y, hv.x, acc[1][0]); acc[1][1] = fmaf(wv.y, hv.y, acc[1][1]);
            acc[2][0] = fmaf(wv.z, hv.x, acc[2][0]); acc[2][1] = fmaf(wv.z, hv.y, acc[2][1]);
            acc[3][0] = fmaf(wv.w, hv.x, acc[3][0]); acc[3][1] = fmaf(wv.w, hv.y, acc[3][1]);
        }
        #pragma unroll
        for (int a = 0; a < 4; ++a) {
            sh2T[(q0 + a) * 32 + gb]     = tanha(acc[a][0]);
            sh2T[(q0 + a) * 32 + gb + 1] = tanha(acc[a][1]);
        }
    }
    __syncthreads();

    // ---- stage 3: head, parallel over 4 p-chunks of 20 ----
    if (tid < od * 128) {
        int g = tid & 31;
        int r = tid >> 5;
        int d = r % od;
        int chunk = r / od;             // 0..3
        int pbase = chunk * 20;
        float acc = 0.0f;
        #pragma unroll 5
        for (int p = 0; p < 20; ++p)
            acc = fmaf(sh2T[(pbase + p) * 32 + g], shw[(pbase + p) * od + d], acc);
        hpart[(chunk * od + d) * 32 + g] = acc;
    }
    __syncthreads();
    if (tid < od * 32) {
        int g = tid & 31;
        int d = tid >> 5;
        float acc = shb[d];
        #pragma unroll
        for (int c = 0; c < 4; ++c) acc += hpart[(c * od + d) * 32 + g];
        int i = g0 + g;
        if      (m == 0) out[i * 6 + 0]     = sprm[g * 9 + 2]     + acc;
        else if (m == 1) out[i * 6 + 1 + d] = sprm[g * 9 + d]     + acc;
        else if (m == 2) out[i * 6 + 3 + d] = sprm[g * 9 + 3 + d] * __expf(acc);
        else             out[i * 6 + 5]     = sprm[g * 9 + 5]     + acc;
    }
}

// ---------------------------------------------------------------------------
extern "C" void kernel_launch(void* const* d_in, const int* in_sizes, int n_in,
                              void* d_out, int out_size)
{
    const float* means     = (const float*)d_in[0];
    const float* u         = (const float*)d_in[1];
    const float* scaling   = (const float*)d_in[2];
    const float* transform = (const float*)d_in[3];
    const float* conv_w    = (const float*)d_in[4];
    const float* conv_b    = (const float*)d_in[5];
    const float* emb_w     = (const float*)d_in[6];
    const float* emb_b     = (const float*)d_in[7];
    const float* lin1_w    = (const float*)d_in[8];
    const float* lin1_b    = (const float*)d_in[9];
    const float* sol_w     = (const float*)d_in[10];
    const float* sol_b     = (const float*)d_in[11];
    const float* tr_w      = (const float*)d_in[12];
    const float* tr_b      = (const float*)d_in[13];
    const float* sc_w      = (const float*)d_in[14];
    const float* sc_b      = (const float*)d_in[15];
    const float* tf_w      = (const float*)d_in[16];
    const float* tf_b      = (const float*)d_in[17];
    float* out             = (float*)d_out;

    static int smem_set = 0;
    if (!smem_set) {
        cudaFuncSetAttribute(k_net, cudaFuncAttributeMaxDynamicSharedMemorySize,
                             SMEM_FLTS * (int)sizeof(float));
        smem_set = 1;
    }

    k_samples<<<N_G * 25 / 128, 128>>>(means, u, scaling, transform);
    dim3 grid(4, N_G / GPB, 1);
    k_net<<<grid, 512, SMEM_FLTS * sizeof(float)>>>(
        conv_w, conv_b, emb_w, emb_b, lin1_w, lin1_b,
        sol_w, sol_b, tr_w, tr_b, sc_w, sc_b, tf_w, tf_b,
        means, u, scaling, transform, out);
}

// round 8
// speedup vs baseline: 1.0918x; 1.0918x over previous
#include <cuda_runtime.h>
#include <math.h>

#define N_G   1024
#define SCALE 1.0f
#define DXC   (2.0f / 31.0f)
#define QCUT  60.0f                // dropped terms < e^-30 of dominant: negligible
#define GPB   16                   // gaussians per block in net kernel
#define CANDCAP 512

__device__ float d_img[N_G * 75];  // (N, 3, 5, 5): c*25 + kx*5 + ky

__device__ __forceinline__ float tanha(float x) {
    float y;
    asm("tanh.approx.f32 %0, %1;" : "=f"(y) : "f"(x));
    return y;
}

// ---------------------------------------------------------------------------
// Kernel 1: sampling with per-block candidate list (unchanged, known-good).
// ---------------------------------------------------------------------------
__global__ void __launch_bounds__(128) k_samples(
    const float* __restrict__ means, const float* __restrict__ u,
    const float* __restrict__ scaling, const float* __restrict__ transform)
{
    __shared__ float4 cA[CANDCAP];
    __shared__ float4 cB[CANDCAP];
    __shared__ int    s_wcnt[4], s_wbase[4], s_total;
    __shared__ float  s_bb[4];
    __shared__ float  s_red[4][4];

    const int tid = threadIdx.x;
    if (tid == 0) s_total = 0;

    const int s  = blockIdx.x * 128 + tid;
    const int i  = s / 25;
    const int k  = s % 25;
    const int kx = k / 5;
    const int ky = k % 5;
    const float sx = means[2 * i]     + (float)(kx - 2) * DXC;
    const float sy = means[2 * i + 1] + (float)(ky - 2) * DXC;

    float mnx = sx, mxx = sx, mny = sy, mxy = sy;
    #pragma unroll
    for (int o = 16; o > 0; o >>= 1) {
        mnx = fminf(mnx, __shfl_xor_sync(0xffffffffu, mnx, o));
        mxx = fmaxf(mxx, __shfl_xor_sync(0xffffffffu, mxx, o));
        mny = fminf(mny, __shfl_xor_sync(0xffffffffu, mny, o));
        mxy = fmaxf(mxy, __shfl_xor_sync(0xffffffffu, mxy, o));
    }
    if ((tid & 31) == 0) {
        s_red[tid >> 5][0] = mnx; s_red[tid >> 5][1] = mxx;
        s_red[tid >> 5][2] = mny; s_red[tid >> 5][3] = mxy;
    }
    __syncthreads();
    if (tid == 0) {
        float a0 = s_red[0][0], a1 = s_red[0][1], a2 = s_red[0][2], a3 = s_red[0][3];
        for (int w2 = 1; w2 < 4; ++w2) {
            a0 = fminf(a0, s_red[w2][0]); a1 = fmaxf(a1, s_red[w2][1]);
            a2 = fminf(a2, s_red[w2][2]); a3 = fmaxf(a3, s_red[w2][3]);
        }
        s_bb[0] = a0; s_bb[1] = a1; s_bb[2] = a2; s_bb[3] = a3;
    }
    __syncthreads();
    const float bminx = s_bb[0], bmaxx = s_bb[1], bminy = s_bb[2], bmaxy = s_bb[3];

    const int wid = tid >> 5, lane = tid & 31;
    for (int c = 0; c < N_G / 128; ++c) {
        int j = c * 128 + tid;
        float mx = means[2 * j], my = means[2 * j + 1];
        float s0 = scaling[2 * j], s1 = scaling[2 * j + 1], t = transform[j];
        float A = s0 * s0, B = s0 * t, C = t * t + s1 * s1;
        float inv = 1.0f / (A * C - B * B);
        float ca =  C * inv, cb = -B * inv, cc = A * inv;
        float h = 0.5f * (A + C);
        float r = sqrtf(0.25f * (A - C) * (A - C) + B * B);
        float r2max = QCUT * (h + r);
        float ddx = fmaxf(fmaxf(bminx - mx, mx - bmaxx), 0.0f);
        float ddy = fmaxf(fmaxf(bminy - my, my - bmaxy), 0.0f);
        bool pred = (ddx * ddx + ddy * ddy) <= r2max;
        unsigned bm = __ballot_sync(0xffffffffu, pred);
        if (lane == 0) s_wcnt[wid] = __popc(bm);
        __syncthreads();
        if (tid == 0) {
            int acc = s_total;
            for (int w2 = 0; w2 < 4; ++w2) { s_wbase[w2] = acc; acc += s_wcnt[w2]; }
            s_total = acc;
        }
        __syncthreads();
        if (pred) {
            int idx = s_wbase[wid] + __popc(bm & ((1u << lane) - 1u));
            if (idx < CANDCAP) {
                cA[idx] = make_float4(mx, my, r2max, u[j]);
                cB[idx] = make_float4(ca, cb, cc, ca + cc);
            }
        }
        __syncthreads();
    }
    int cnt = s_total;
    if (cnt > CANDCAP) cnt = CANDCAP;

    float us = 0.0f, pd = 0.0f;
    for (int t2 = 0; t2 < cnt; ++t2) {
        float4 A  = cA[t2];
        float4 Bv = cB[t2];
        float dx = sx - A.x;
        float dy = sy - A.y;
        float Cd0 = Bv.x * dx + Bv.y * dy;
        float Cd1 = Bv.y * dx + Bv.z * dy;
        float q   = dx * Cd0 + dy * Cd1;
        float w   = __expf(-0.5f * q) * A.w;
        us += w;
        pd += w * (Cd0 * Cd0 + Cd1 * Cd1 - Bv.w);
    }
    float maskv = (fabsf(sx) < SCALE && fabsf(sy) < SCALE) ? 1.0f : 0.0f;
    d_img[i * 75 +  0 + k] = us;
    d_img[i * 75 + 25 + k] = pd;
    d_img[i * 75 + 50 + k] = maskv;
}

// ---------------------------------------------------------------------------
// Kernel 2: 4 nets, GPB=16, 256 threads, grid (4,64)=256 blocks.
// Stage-2 = 4q x 4g register tiles with 2-way p split; block-level barriers.
// ---------------------------------------------------------------------------
#define OFF_SWC   0        // 3750 (+2 pad)
#define OFF_SWE   3752     // 180
#define OFF_SWL   3932     // 6400
#define OFF_SBC   10332    // 50 (+2)
#define OFF_SBE   10384    // 30 (+2)
#define OFF_SBL   10416    // 80
#define OFF_SHW   10496    // 160
#define OFF_SHB   10656    // 2 (+2)
#define OFF_SPRM  10660    // 16*9 = 144
#define OFF_IMGT  10804    // 75*16 = 1200
#define OFF_SHT   12004    // 80*16 = 1280
#define OFF_SH2T  13284    // 80*16 = 1280
#define OFF_PP    14564    // 80*16 = 1280 (stage-2 partials)
#define OFF_HP    15844    // 128
#define SMEM_FLTS 15972

__global__ void __launch_bounds__(256) k_net(
    const float* __restrict__ conv_w, const float* __restrict__ conv_b,
    const float* __restrict__ emb_w,  const float* __restrict__ emb_b,
    const float* __restrict__ lin1_w, const float* __restrict__ lin1_b,
    const float* __restrict__ sol_w,  const float* __restrict__ sol_b,
    const float* __restrict__ tr_w,   const float* __restrict__ tr_b,
    const float* __restrict__ sc_w,   const float* __restrict__ sc_b,
    const float* __restrict__ tf_w,   const float* __restrict__ tf_b,
    const float* __restrict__ means,  const float* __restrict__ u,
    const float* __restrict__ scaling,const float* __restrict__ transform,
    float* __restrict__ out)
{
    extern __shared__ float sm[];
    float* swc  = sm + OFF_SWC;
    float* swe  = sm + OFF_SWE;
    float* swl  = sm + OFF_SWL;
    float* sbc  = sm + OFF_SBC;
    float* sbe  = sm + OFF_SBE;
    float* sbl  = sm + OFF_SBL;
    float* shw  = sm + OFF_SHW;
    float* shb  = sm + OFF_SHB;
    float* sprm = sm + OFF_SPRM;
    float* imgT = sm + OFF_IMGT;
    float* shT  = sm + OFF_SHT;
    float* sh2T = sm + OFF_SH2T;
    float* pp   = sm + OFF_PP;
    float* hpart= sm + OFF_HP;

    const int m   = blockIdx.x;
    const int g0  = blockIdx.y * GPB;
    const int tid = threadIdx.x;
    const int od  = (m == 1 || m == 2) ? 2 : 1;

    // ---- vectorized weight loads ----
    {
        const float4* lw4 = (const float4*)(lin1_w + m * 6400);
        float4* sl4 = (float4*)swl;
        for (int idx = tid; idx < 1600; idx += 256) sl4[idx] = lw4[idx];
        const float2* cw2 = (const float2*)(conv_w + m * 3750);
        float2* sc2 = (float2*)swc;
        for (int idx = tid; idx < 1875; idx += 256) sc2[idx] = cw2[idx];
        const float2* ew2 = (const float2*)(emb_w + m * 180);
        float2* se2 = (float2*)swe;
        if (tid < 90) se2[tid] = ew2[tid];
    }
    if (tid < 50) sbc[tid] = conv_b[m * 50 + tid];
    if (tid >= 64 && tid < 94)  sbe[tid - 64] = emb_b[m * 30 + (tid - 64)];
    if (tid >= 96 && tid < 176) sbl[tid - 96] = lin1_b[m * 80 + (tid - 96)];
    const float* hw; const float* hb;
    if      (m == 0) { hw = sol_w; hb = sol_b; }
    else if (m == 1) { hw = tr_w;  hb = tr_b;  }
    else if (m == 2) { hw = sc_w;  hb = sc_b;  }
    else             { hw = tf_w;  hb = tf_b;  }
    // FIX: full strided load of head weights (up to 160 elements)
    for (int idx = tid; idx < 80 * od; idx += 256) shw[idx] = hw[idx];
    if (tid < od) shb[tid] = hb[tid];
    if (tid >= 224 && tid < 224 + GPB) {
        int g = tid - 224, i = g0 + g;
        sprm[g * 9 + 0] = means[2 * i];
        sprm[g * 9 + 1] = means[2 * i + 1];
        sprm[g * 9 + 2] = u[i];
        sprm[g * 9 + 3] = scaling[2 * i];
        sprm[g * 9 + 4] = scaling[2 * i + 1];
        sprm[g * 9 + 5] = transform[i];
    }
    for (int idx = tid; idx < GPB * 75; idx += 256) {
        int g = idx / 75, kk = idx - g * 75;
        imgT[kk * 16 + g] = d_img[(g0 + g) * 75 + kk];
    }
    __syncthreads();

    // ---- stage 1: conv (tid<100: 2o x 4g) + emb (tid 128..247: 1q x 4g) ----
    if (tid < 100) {
        int o0 = (tid >> 2) * 2;
        int gb = (tid & 3) * 4;
        float b0 = sbc[o0], b1 = sbc[o0 + 1];
        float acc0[4] = {b0, b0, b0, b0};
        float acc1[4] = {b1, b1, b1, b1};
        const float* w0r = &swc[o0 * 75];
        const float* w1r = &swc[(o0 + 1) * 75];
        #pragma unroll 5
        for (int kk = 0; kk < 75; ++kk) {
            float w0 = w0r[kk], w1 = w1r[kk];
            float4 v = *(const float4*)&imgT[kk * 16 + gb];
            acc0[0] = fmaf(w0, v.x, acc0[0]); acc1[0] = fmaf(w1, v.x, acc1[0]);
            acc0[1] = fmaf(w0, v.y, acc0[1]); acc1[1] = fmaf(w1, v.y, acc1[1]);
            acc0[2] = fmaf(w0, v.z, acc0[2]); acc1[2] = fmaf(w1, v.z, acc1[2]);
            acc0[3] = fmaf(w0, v.w, acc0[3]); acc1[3] = fmaf(w1, v.w, acc1[3]);
        }
        #pragma unroll
        for (int b = 0; b < 4; ++b) {
            shT[o0 * 16 + gb + b]       = tanha(acc0[b]);
            shT[(o0 + 1) * 16 + gb + b] = tanha(acc1[b]);
        }
    } else if (tid >= 128 && tid < 248) {
        int et = tid - 128;
        int q  = et >> 2;               // 0..29
        int gb = (et & 3) * 4;
        float be = sbe[q];
        float acc[4] = {be, be, be, be};
        #pragma unroll
        for (int p = 0; p < 6; ++p) {
            float w = swe[p * 30 + q];
            acc[0] = fmaf(sprm[(gb + 0) * 9 + p], w, acc[0]);
            acc[1] = fmaf(sprm[(gb + 1) * 9 + p], w, acc[1]);
            acc[2] = fmaf(sprm[(gb + 2) * 9 + p], w, acc[2]);
            acc[3] = fmaf(sprm[(gb + 3) * 9 + p], w, acc[3]);
        }
        #pragma unroll
        for (int b = 0; b < 4; ++b) shT[(50 + q) * 16 + gb + b] = tanha(acc[b]);
    }
    __syncthreads();

    // ---- stage 2: 80x80 as 4q x 4g tiles, 2-way p split; barriers block-wide ----
    {
        const bool active = (tid < 160);
        int hhalf = 0, q0 = 0, gb = 0;
        float acc[4][4];
        #pragma unroll
        for (int a = 0; a < 4; ++a)
            #pragma unroll
            for (int b = 0; b < 4; ++b) acc[a][b] = 0.0f;
        if (active) {
            hhalf = tid / 80;             // p-half 0/1
            int r = tid - hhalf * 80;     // 0..79
            q0    = (r >> 2) * 4;         // 0..76
            gb    = (r & 3) * 4;          // 0,4,8,12
            int pbase = hhalf * 40;
            #pragma unroll 4
            for (int p = pbase; p < pbase + 40; ++p) {
                float4 wv = *(const float4*)&swl[p * 80 + q0];
                float4 hv = *(const float4*)&shT[p * 16 + gb];
                acc[0][0] = fmaf(wv.x, hv.x, acc[0][0]); acc[0][1] = fmaf(wv.x, hv.y, acc[0][1]);
                acc[0][2] = fmaf(wv.x, hv.z, acc[0][2]); acc[0][3] = fmaf(wv.x, hv.w, acc[0][3]);
                acc[1][0] = fmaf(wv.y, hv.x, acc[1][0]); acc[1][1] = fmaf(wv.y, hv.y, acc[1][1]);
                acc[1][2] = fmaf(wv.y, hv.z, acc[1][2]); acc[1][3] = fmaf(wv.y, hv.w, acc[1][3]);
                acc[2][0] = fmaf(wv.z, hv.x, acc[2][0]); acc[2][1] = fmaf(wv.z, hv.y, acc[2][1]);
                acc[2][2] = fmaf(wv.z, hv.z, acc[2][2]); acc[2][3] = fmaf(wv.z, hv.w, acc[2][3]);
                acc[3][0] = fmaf(wv.w, hv.x, acc[3][0]); acc[3][1] = fmaf(wv.w, hv.y, acc[3][1]);
                acc[3][2] = fmaf(wv.w, hv.z, acc[3][2]); acc[3][3] = fmaf(wv.w, hv.w, acc[3][3]);
            }
        }
        if (active && hhalf == 0) {
            #pragma unroll
            for (int a = 0; a < 4; ++a)
                #pragma unroll
                for (int b = 0; b < 4; ++b)
                    pp[(q0 + a) * 16 + gb + b] = acc[a][b];
        }
        __syncthreads();                  // block-wide: half-0 partials visible
        if (active && hhalf == 1) {
            #pragma unroll
            for (int a = 0; a < 4; ++a) {
                float bl = sbl[q0 + a];
                #pragma unroll
                for (int b = 0; b < 4; ++b)
                    sh2T[(q0 + a) * 16 + gb + b] =
                        tanha(bl + acc[a][b] + pp[(q0 + a) * 16 + gb + b]);
            }
        }
    }
    __syncthreads();

    // ---- stage 3: head, parallel over 4 p-chunks of 20 ----
    if (tid < od * 64) {
        int g = tid & 15;
        int r = tid >> 4;
        int d = r % od;
        int chunk = r / od;             // 0..3
        int pbase = chunk * 20;
        float acc = 0.0f;
        #pragma unroll 5
        for (int p = 0; p < 20; ++p)
            acc = fmaf(sh2T[(pbase + p) * 16 + g], shw[(pbase + p) * od + d], acc);
        hpart[(chunk * od + d) * 16 + g] = acc;
    }
    __syncthreads();
    if (tid < od * 16) {
        int g = tid & 15;
        int d = tid >> 4;
        float acc = shb[d];
        #pragma unroll
        for (int c = 0; c < 4; ++c) acc += hpart[(c * od + d) * 16 + g];
        int i = g0 + g;
        if      (m == 0) out[i * 6 + 0]     = sprm[g * 9 + 2]     + acc;
        else if (m == 1) out[i * 6 + 1 + d] = sprm[g * 9 + d]     + acc;
        else if (m == 2) out[i * 6 + 3 + d] = sprm[g * 9 + 3 + d] * __expf(acc);
        else             out[i * 6 + 5]     = sprm[g * 9 + 5]     + acc;
    }
}

// ---------------------------------------------------------------------------
extern "C" void kernel_launch(void* const* d_in, const int* in_sizes, int n_in,
                              void* d_out, int out_size)
{
    const float* means     = (const float*)d_in[0];
    const float* u         = (const float*)d_in[1];
    const float* scaling   = (const float*)d_in[2];
    const float* transform = (const float*)d_in[3];
    const float* conv_w    = (const float*)d_in[4];
    const float* conv_b    = (const float*)d_in[5];
    const float* emb_w     = (const float*)d_in[6];
    const float* emb_b     = (const float*)d_in[7];
    const float* lin1_w    = (const float*)d_in[8];
    const float* lin1_b    = (const float*)d_in[9];
    const float* sol_w     = (const float*)d_in[10];
    const float* sol_b     = (const float*)d_in[11];
    const float* tr_w      = (const float*)d_in[12];
    const float* tr_b      = (const float*)d_in[13];
    const float* sc_w      = (const float*)d_in[14];
    const float* sc_b      = (const float*)d_in[15];
    const float* tf_w      = (const float*)d_in[16];
    const float* tf_b      = (const float*)d_in[17];
    float* out             = (float*)d_out;

    static int smem_set = 0;
    if (!smem_set) {
        cudaFuncSetAttribute(k_net, cudaFuncAttributeMaxDynamicSharedMemorySize,
                             SMEM_FLTS * (int)sizeof(float));
        smem_set = 1;
    }

    k_samples<<<N_G * 25 / 128, 128>>>(means, u, scaling, transform);
    dim3 grid(4, N_G / GPB, 1);
    k_net<<<grid, 256, SMEM_FLTS * sizeof(float)>>>(
        conv_w, conv_b, emb_w, emb_b, lin1_w, lin1_b,
        sol_w, sol_b, tr_w, tr_b, sc_w, sc_b, tf_w, tf_b,
        means, u, scaling, transform, out);
}

// round 9
// speedup vs baseline: 1.2125x; 1.1105x over previous
#include <cuda_runtime.h>
#include <math.h>

#define N_G   1024
#define SCALE 1.0f
#define DXC   (2.0f / 31.0f)
#define QCUT  60.0f                // dropped terms < e^-30 of dominant: negligible
#define GPB   16                   // gaussians per block (phase B)
#define CANDCAP 512
#define GRID_TOTAL 256

__device__ float d_img[N_G * 75];  // (N, 3, 5, 5): c*25 + kx*5 + ky
__device__ unsigned g_arrive;      // zero-init; reset at end of every run
__device__ unsigned g_depart;

__device__ __forceinline__ float tanha(float x) {
    float y;
    asm("tanh.approx.f32 %0, %1;" : "=f"(y) : "f"(x));
    return y;
}

// ---- dynamic smem layout (float offsets), all regions 16B-aligned ----
#define OFF_SWC   0        // 3750 (+2 pad)
#define OFF_SWE   3752     // 180
#define OFF_SWL   3932     // 6400
#define OFF_SBC   10332    // 50 (+2)
#define OFF_SBE   10384    // 30 (+2)
#define OFF_SBL   10416    // 80
#define OFF_SHW   10496    // 160
#define OFF_SHB   10656    // 2 (+2)
#define OFF_SPRM  10660    // 16*9 = 144
#define OFF_IMGT  10804    // 75*16 = 1200
#define OFF_SHT   12004    // 80*16 = 1280
#define OFF_SH2T  13284    // 80*16 = 1280
#define OFF_PP    14564    // 80*16 = 1280 (stage-2 partials, chunk 0)
#define OFF_PP2   15844    // 80*16 = 1280 (stage-2 partials, chunk 1)
#define OFF_HP    17124    // 128
#define SMEM_FLTS 17252    // 69008 bytes -> 3 blocks/SM -> capacity 444 >= 256

__global__ void __launch_bounds__(256) k_all(
    const float* __restrict__ means,  const float* __restrict__ u,
    const float* __restrict__ scaling,const float* __restrict__ transform,
    const float* __restrict__ conv_w, const float* __restrict__ conv_b,
    const float* __restrict__ emb_w,  const float* __restrict__ emb_b,
    const float* __restrict__ lin1_w, const float* __restrict__ lin1_b,
    const float* __restrict__ sol_w,  const float* __restrict__ sol_b,
    const float* __restrict__ tr_w,   const float* __restrict__ tr_b,
    const float* __restrict__ sc_w,   const float* __restrict__ sc_b,
    const float* __restrict__ tf_w,   const float* __restrict__ tf_b,
    float* __restrict__ out)
{
    extern __shared__ float sm[];
    const int b   = blockIdx.x;
    const int tid = threadIdx.x;

    // =================== PHASE A: sampling for gaussians [4b, 4b+4) ==========
    {
        float4* cA = (float4*)sm;                 // 512 float4
        float4* cB = (float4*)(sm + 2048);        // 512 float4
        int* s_wcnt  = (int*)(sm + 4096);         // 8
        int* s_wbase = (int*)(sm + 4104);         // 8
        int* s_total = (int*)(sm + 4112);

        if (tid == 0) *s_total = 0;
        __syncthreads();

        // tight bbox over this block's 4 gaussians
        const int i0 = b * 4;
        float bminx = 1e30f, bmaxx = -1e30f, bminy = 1e30f, bmaxy = -1e30f;
        #pragma unroll
        for (int g = 0; g < 4; ++g) {
            float mx = means[2 * (i0 + g)], my = means[2 * (i0 + g) + 1];
            bminx = fminf(bminx, mx); bmaxx = fmaxf(bmaxx, mx);
            bminy = fminf(bminy, my); bmaxy = fmaxf(bmaxy, my);
        }
        bminx -= 2.0f * DXC; bmaxx += 2.0f * DXC;
        bminy -= 2.0f * DXC; bmaxy += 2.0f * DXC;

        // candidate scan (4 rounds of 256), deterministic compaction
        const int wid = tid >> 5, lane = tid & 31;
        for (int c = 0; c < N_G / 256; ++c) {
            int j = c * 256 + tid;
            float mx = means[2 * j], my = means[2 * j + 1];
            float s0 = scaling[2 * j], s1 = scaling[2 * j + 1], t = transform[j];
            float A = s0 * s0, B = s0 * t, C = t * t + s1 * s1;
            float inv = 1.0f / (A * C - B * B);
            float ca =  C * inv, cb = -B * inv, cc = A * inv;
            float h = 0.5f * (A + C);
            float r = sqrtf(0.25f * (A - C) * (A - C) + B * B);
            float r2max = QCUT * (h + r);
            float ddx = fmaxf(fmaxf(bminx - mx, mx - bmaxx), 0.0f);
            float ddy = fmaxf(fmaxf(bminy - my, my - bmaxy), 0.0f);
            bool pred = (ddx * ddx + ddy * ddy) <= r2max;
            unsigned bm = __ballot_sync(0xffffffffu, pred);
            if (lane == 0) s_wcnt[wid] = __popc(bm);
            __syncthreads();
            if (tid == 0) {
                int acc = *s_total;
                for (int w2 = 0; w2 < 8; ++w2) { s_wbase[w2] = acc; acc += s_wcnt[w2]; }
                *s_total = acc;
            }
            __syncthreads();
            if (pred) {
                int idx = s_wbase[wid] + __popc(bm & ((1u << lane) - 1u));
                if (idx < CANDCAP) {
                    cA[idx] = make_float4(mx, my, r2max, u[j]);
                    cB[idx] = make_float4(ca, cb, cc, ca + cc);
                }
            }
            __syncthreads();
        }
        int cnt = *s_total;
        if (cnt > CANDCAP) cnt = CANDCAP;

        // evaluate 100 samples (threads 0..99)
        if (tid < 100) {
            const int s  = b * 100 + tid;
            const int i  = s / 25;
            const int k  = s % 25;
            const int kx = k / 5, ky = k % 5;
            const float sx = means[2 * i]     + (float)(kx - 2) * DXC;
            const float sy = means[2 * i + 1] + (float)(ky - 2) * DXC;
            float us = 0.0f, pd = 0.0f;
            for (int t2 = 0; t2 < cnt; ++t2) {
                float4 A  = cA[t2];
                float4 Bv = cB[t2];
                float dx = sx - A.x;
                float dy = sy - A.y;
                float Cd0 = Bv.x * dx + Bv.y * dy;
                float Cd1 = Bv.y * dx + Bv.z * dy;
                float q   = dx * Cd0 + dy * Cd1;
                float w   = __expf(-0.5f * q) * A.w;
                us += w;
                pd += w * (Cd0 * Cd0 + Cd1 * Cd1 - Bv.w);
            }
            float maskv = (fabsf(sx) < SCALE && fabsf(sy) < SCALE) ? 1.0f : 0.0f;
            d_img[i * 75 +  0 + k] = us;
            d_img[i * 75 + 25 + k] = pd;
            d_img[i * 75 + 50 + k] = maskv;
        }
    }

    // =================== GRID BARRIER (co-residency guaranteed) ==============
    __threadfence();
    __syncthreads();
    if (tid == 0) {
        atomicAdd(&g_arrive, 1u);
        while (atomicAdd(&g_arrive, 0u) < GRID_TOTAL) { }
    }
    __syncthreads();

    // =================== PHASE B: the 4 networks =============================
    float* swc  = sm + OFF_SWC;
    float* swe  = sm + OFF_SWE;
    float* swl  = sm + OFF_SWL;
    float* sbc  = sm + OFF_SBC;
    float* sbe  = sm + OFF_SBE;
    float* sbl  = sm + OFF_SBL;
    float* shw  = sm + OFF_SHW;
    float* shb  = sm + OFF_SHB;
    float* sprm = sm + OFF_SPRM;
    float* imgT = sm + OFF_IMGT;
    float* shT  = sm + OFF_SHT;
    float* sh2T = sm + OFF_SH2T;
    float* pp   = sm + OFF_PP;
    float* pp2  = sm + OFF_PP2;
    float* hpart= sm + OFF_HP;

    const int m  = b & 3;
    const int g0 = (b >> 2) * GPB;
    const int od = (m == 1 || m == 2) ? 2 : 1;

    // ---- vectorized weight loads ----
    {
        const float4* lw4 = (const float4*)(lin1_w + m * 6400);
        float4* sl4 = (float4*)swl;
        for (int idx = tid; idx < 1600; idx += 256) sl4[idx] = lw4[idx];
        const float2* cw2 = (const float2*)(conv_w + m * 3750);
        float2* sc2 = (float2*)swc;
        for (int idx = tid; idx < 1875; idx += 256) sc2[idx] = cw2[idx];
        const float2* ew2 = (const float2*)(emb_w + m * 180);
        float2* se2 = (float2*)swe;
        if (tid < 90) se2[tid] = ew2[tid];
    }
    if (tid < 50) sbc[tid] = conv_b[m * 50 + tid];
    if (tid >= 64 && tid < 94)  sbe[tid - 64] = emb_b[m * 30 + (tid - 64)];
    if (tid >= 96 && tid < 176) sbl[tid - 96] = lin1_b[m * 80 + (tid - 96)];
    const float* hw; const float* hb;
    if      (m == 0) { hw = sol_w; hb = sol_b; }
    else if (m == 1) { hw = tr_w;  hb = tr_b;  }
    else if (m == 2) { hw = sc_w;  hb = sc_b;  }
    else             { hw = tf_w;  hb = tf_b;  }
    for (int idx = tid; idx < 80 * od; idx += 256) shw[idx] = hw[idx];
    if (tid < od) shb[tid] = hb[tid];
    if (tid >= 224 && tid < 224 + GPB) {
        int g = tid - 224, i = g0 + g;
        sprm[g * 9 + 0] = means[2 * i];
        sprm[g * 9 + 1] = means[2 * i + 1];
        sprm[g * 9 + 2] = u[i];
        sprm[g * 9 + 3] = scaling[2 * i];
        sprm[g * 9 + 4] = scaling[2 * i + 1];
        sprm[g * 9 + 5] = transform[i];
    }
    for (int idx = tid; idx < GPB * 75; idx += 256) {
        int g = idx / 75, kk = idx - g * 75;
        imgT[kk * 16 + g] = d_img[(g0 + g) * 75 + kk];
    }
    __syncthreads();

    // ---- stage 1: conv on 200 threads (1o x 4g) + emb on threads 200..255 ----
    if (tid < 200) {
        int o  = tid >> 2;              // 0..49
        int gb = (tid & 3) * 4;
        float acc[4];
        float b0 = sbc[o];
        acc[0] = b0; acc[1] = b0; acc[2] = b0; acc[3] = b0;
        const float* wr = &swc[o * 75];
        #pragma unroll 5
        for (int kk = 0; kk < 75; ++kk) {
            float w = wr[kk];
            float4 v = *(const float4*)&imgT[kk * 16 + gb];
            acc[0] = fmaf(w, v.x, acc[0]); acc[1] = fmaf(w, v.y, acc[1]);
            acc[2] = fmaf(w, v.z, acc[2]); acc[3] = fmaf(w, v.w, acc[3]);
        }
        #pragma unroll
        for (int bb = 0; bb < 4; ++bb) shT[o * 16 + gb + bb] = tanha(acc[bb]);
    } else {
        int et = tid - 200;             // 0..55
        for (int task = et; task < 120; task += 56) {
            int q  = task >> 2;         // 0..29
            int gb = (task & 3) * 4;
            float be = sbe[q];
            float acc[4] = {be, be, be, be};
            #pragma unroll
            for (int p = 0; p < 6; ++p) {
                float w = swe[p * 30 + q];
                acc[0] = fmaf(sprm[(gb + 0) * 9 + p], w, acc[0]);
                acc[1] = fmaf(sprm[(gb + 1) * 9 + p], w, acc[1]);
                acc[2] = fmaf(sprm[(gb + 2) * 9 + p], w, acc[2]);
                acc[3] = fmaf(sprm[(gb + 3) * 9 + p], w, acc[3]);
            }
            #pragma unroll
            for (int bb = 0; bb < 4; ++bb) shT[(50 + q) * 16 + gb + bb] = tanha(acc[bb]);
        }
    }
    __syncthreads();

    // ---- stage 2: 80x80 as 4q x 4g tiles, 3-way p split (240 threads) ----
    {
        const bool active = (tid < 240);
        int chunk = 0, q0 = 0, gb = 0, pst = 0, pen = 0;
        float acc[4][4];
        #pragma unroll
        for (int a = 0; a < 4; ++a)
            #pragma unroll
            for (int bb = 0; bb < 4; ++bb) acc[a][bb] = 0.0f;
        if (active) {
            chunk = tid / 80;            // 0,1,2
            int r = tid - chunk * 80;    // 0..79
            q0  = (r >> 2) * 4;          // 0..76
            gb  = (r & 3) * 4;           // 0,4,8,12
            pst = chunk * 27;
            pen = (chunk == 2) ? 80 : pst + 27;
            #pragma unroll 3
            for (int p = pst; p < pen; ++p) {
                float4 wv = *(const float4*)&swl[p * 80 + q0];
                float4 hv = *(const float4*)&shT[p * 16 + gb];
                acc[0][0] = fmaf(wv.x, hv.x, acc[0][0]); acc[0][1] = fmaf(wv.x, hv.y, acc[0][1]);
                acc[0][2] = fmaf(wv.x, hv.z, acc[0][2]); acc[0][3] = fmaf(wv.x, hv.w, acc[0][3]);
                acc[1][0] = fmaf(wv.y, hv.x, acc[1][0]); acc[1][1] = fmaf(wv.y, hv.y, acc[1][1]);
                acc[1][2] = fmaf(wv.y, hv.z, acc[1][2]); acc[1][3] = fmaf(wv.y, hv.w, acc[1][3]);
                acc[2][0] = fmaf(wv.z, hv.x, acc[2][0]); acc[2][1] = fmaf(wv.z, hv.y, acc[2][1]);
                acc[2][2] = fmaf(wv.z, hv.z, acc[2][2]); acc[2][3] = fmaf(wv.z, hv.w, acc[2][3]);
                acc[3][0] = fmaf(wv.w, hv.x, acc[3][0]); acc[3][1] = fmaf(wv.w, hv.y, acc[3][1]);
                acc[3][2] = fmaf(wv.w, hv.z, acc[3][2]); acc[3][3] = fmaf(wv.w, hv.w, acc[3][3]);
            }
        }
        if (active && chunk == 0) {
            #pragma unroll
            for (int a = 0; a < 4; ++a)
                #pragma unroll
                for (int bb = 0; bb < 4; ++bb)
                    pp[(q0 + a) * 16 + gb + bb] = acc[a][bb];
        }
        if (active && chunk == 1) {
            #pragma unroll
            for (int a = 0; a < 4; ++a)
                #pragma unroll
                for (int bb = 0; bb < 4; ++bb)
                    pp2[(q0 + a) * 16 + gb + bb] = acc[a][bb];
        }
        __syncthreads();                  // block-wide
        if (active && chunk == 2) {
            #pragma unroll
            for (int a = 0; a < 4; ++a) {
                float bl = sbl[q0 + a];
                #pragma unroll
                for (int bb = 0; bb < 4; ++bb)
                    sh2T[(q0 + a) * 16 + gb + bb] =
                        tanha(bl + acc[a][bb] + pp[(q0 + a) * 16 + gb + bb]
                                              + pp2[(q0 + a) * 16 + gb + bb]);
            }
        }
    }
    __syncthreads();

    // ---- stage 3: head, parallel over 4 p-chunks of 20 ----
    if (tid < od * 64) {
        int g = tid & 15;
        int r = tid >> 4;
        int d = r % od;
        int chunk = r / od;             // 0..3
        int pbase = chunk * 20;
        float acc = 0.0f;
        #pragma unroll 5
        for (int p = 0; p < 20; ++p)
            acc = fmaf(sh2T[(pbase + p) * 16 + g], shw[(pbase + p) * od + d], acc);
        hpart[(chunk * od + d) * 16 + g] = acc;
    }
    __syncthreads();
    if (tid < od * 16) {
        int g = tid & 15;
        int d = tid >> 4;
        float acc = shb[d];
        #pragma unroll
        for (int c = 0; c < 4; ++c) acc += hpart[(c * od + d) * 16 + g];
        int i = g0 + g;
        if      (m == 0) out[i * 6 + 0]     = sprm[g * 9 + 2]     + acc;
        else if (m == 1) out[i * 6 + 1 + d] = sprm[g * 9 + d]     + acc;
        else if (m == 2) out[i * 6 + 3 + d] = sprm[g * 9 + 3 + d] * __expf(acc);
        else             out[i * 6 + 5]     = sprm[g * 9 + 5]     + acc;
    }

    // ---- barrier counter reset (last block out restores initial state) ----
    __syncthreads();
    if (tid == 0) {
        unsigned d = atomicAdd(&g_depart, 1u) + 1u;
        if (d == GRID_TOTAL) { g_arrive = 0u; g_depart = 0u; __threadfence(); }
    }
}

// ---------------------------------------------------------------------------
extern "C" void kernel_launch(void* const* d_in, const int* in_sizes, int n_in,
                              void* d_out, int out_size)
{
    const float* means     = (const float*)d_in[0];
    const float* u         = (const float*)d_in[1];
    const float* scaling   = (const float*)d_in[2];
    const float* transform = (const float*)d_in[3];
    const float* conv_w    = (const float*)d_in[4];
    const float* conv_b    = (const float*)d_in[5];
    const float* emb_w     = (const float*)d_in[6];
    const float* emb_b     = (const float*)d_in[7];
    const float* lin1_w    = (const float*)d_in[8];
    const float* lin1_b    = (const float*)d_in[9];
    const float* sol_w     = (const float*)d_in[10];
    const float* sol_b     = (const float*)d_in[11];
    const float* tr_w      = (const float*)d_in[12];
    const float* tr_b      = (const float*)d_in[13];
    const float* sc_w      = (const float*)d_in[14];
    const float* sc_b      = (const float*)d_in[15];
    const float* tf_w      = (const float*)d_in[16];
    const float* tf_b      = (const float*)d_in[17];
    float* out             = (float*)d_out;

    static int smem_set = 0;
    if (!smem_set) {
        cudaFuncSetAttribute(k_all, cudaFuncAttributeMaxDynamicSharedMemorySize,
                             SMEM_FLTS * (int)sizeof(float));
        smem_set = 1;
    }

    k_all<<<GRID_TOTAL, 256, SMEM_FLTS * sizeof(float)>>>(
        means, u, scaling, transform,
        conv_w, conv_b, emb_w, emb_b, lin1_w, lin1_b,
        sol_w, sol_b, tr_w, tr_b, sc_w, sc_b, tf_w, tf_b, out);
}

// round 10
// speedup vs baseline: 1.3069x; 1.0779x over previous
#include <cuda_runtime.h>
#include <math.h>

#define N_G   1024
#define SCALE 1.0f
#define DXC   (2.0f / 31.0f)
#define QCUT  60.0f                // dropped terms < e^-30 of dominant: negligible
#define GPB   16                   // gaussians per block (phase B)
#define CANDCAP 512
#define GRID_TOTAL 256

__device__ float d_img[N_G * 75];  // (N, 3, 5, 5): c*25 + kx*5 + ky
__device__ unsigned g_arrive;      // zero-init; reset at end of every run
__device__ unsigned g_depart;

__device__ __forceinline__ float tanha(float x) {
    float y;
    asm("tanh.approx.f32 %0, %1;" : "=f"(y) : "f"(x));
    return y;
}

// ---- dynamic smem layout (float offsets), all regions 16B-aligned ----
// Phase-B weight regions (loaded BEFORE the grid barrier):
#define OFF_SWC   0        // 3750 (+2 pad)
#define OFF_SWE   3752     // 180
#define OFF_SWL   3932     // 6400
#define OFF_SBC   10332    // 50 (+2)
#define OFF_SBE   10384    // 30 (+2)
#define OFF_SBL   10416    // 80
#define OFF_SHW   10496    // 160
#define OFF_SHB   10656    // 2 (+2)
#define OFF_SPRM  10660    // 16*9 = 144
// Phase-B activation buffers (written only AFTER the barrier):
#define OFF_IMGT  10804    // 75*16 = 1200
#define OFF_SHT   12004    // 80*16 = 1280
#define OFF_SH2T  13284    // 80*16 = 1280
#define OFF_PP    14564    // 80*16 = 1280
#define OFF_PP2   15844    // 80*16 = 1280
#define OFF_HP    17124    // 128
#define SMEM_FLTS 17252    // 69008 bytes -> 3 blocks/SM -> capacity 444 >= 256

// Phase-A scratch aliases INTO the phase-B activation region (no conflict:
// phase A finishes before the barrier; activations are written after it).
#define PA_CA    10804             // 512 float4 = 2048 floats
#define PA_CB    12852             // 512 float4 = 2048 floats
#define PA_MISC  14900             // wcnt8 + wbase8 + total
#define PA_PUS   14920             // 100
#define PA_PPD   15020             // 100

__global__ void __launch_bounds__(256) k_all(
    const float* __restrict__ means,  const float* __restrict__ u,
    const float* __restrict__ scaling,const float* __restrict__ transform,
    const float* __restrict__ conv_w, const float* __restrict__ conv_b,
    const float* __restrict__ emb_w,  const float* __restrict__ emb_b,
    const float* __restrict__ lin1_w, const float* __restrict__ lin1_b,
    const float* __restrict__ sol_w,  const float* __restrict__ sol_b,
    const float* __restrict__ tr_w,   const float* __restrict__ tr_b,
    const float* __restrict__ sc_w,   const float* __restrict__ sc_b,
    const float* __restrict__ tf_w,   const float* __restrict__ tf_b,
    float* __restrict__ out)
{
    extern __shared__ float sm[];
    const int b   = blockIdx.x;
    const int tid = threadIdx.x;

    const int m  = b & 3;
    const int g0 = (b >> 2) * GPB;
    const int od = (m == 1 || m == 2) ? 2 : 1;

    // ============ pre-barrier weight loads (overlap with phase A) ============
    {
        const float4* lw4 = (const float4*)(lin1_w + m * 6400);
        float4* sl4 = (float4*)(sm + OFF_SWL);
        for (int idx = tid; idx < 1600; idx += 256) sl4[idx] = lw4[idx];
        const float2* cw2 = (const float2*)(conv_w + m * 3750);
        float2* sc2 = (float2*)(sm + OFF_SWC);
        for (int idx = tid; idx < 1875; idx += 256) sc2[idx] = cw2[idx];
        const float2* ew2 = (const float2*)(emb_w + m * 180);
        float2* se2 = (float2*)(sm + OFF_SWE);
        if (tid < 90) se2[tid] = ew2[tid];
    }
    if (tid < 50) sm[OFF_SBC + tid] = conv_b[m * 50 + tid];
    if (tid >= 64 && tid < 94)  sm[OFF_SBE + tid - 64] = emb_b[m * 30 + (tid - 64)];
    if (tid >= 96 && tid < 176) sm[OFF_SBL + tid - 96] = lin1_b[m * 80 + (tid - 96)];
    {
        const float* hw; const float* hb;
        if      (m == 0) { hw = sol_w; hb = sol_b; }
        else if (m == 1) { hw = tr_w;  hb = tr_b;  }
        else if (m == 2) { hw = sc_w;  hb = sc_b;  }
        else             { hw = tf_w;  hb = tf_b;  }
        for (int idx = tid; idx < 80 * od; idx += 256) sm[OFF_SHW + idx] = hw[idx];
        if (tid < od) sm[OFF_SHB + tid] = hb[tid];
    }
    if (tid >= 224 && tid < 224 + GPB) {
        int g = tid - 224, i = g0 + g;
        sm[OFF_SPRM + g * 9 + 0] = means[2 * i];
        sm[OFF_SPRM + g * 9 + 1] = means[2 * i + 1];
        sm[OFF_SPRM + g * 9 + 2] = u[i];
        sm[OFF_SPRM + g * 9 + 3] = scaling[2 * i];
        sm[OFF_SPRM + g * 9 + 4] = scaling[2 * i + 1];
        sm[OFF_SPRM + g * 9 + 5] = transform[i];
    }

    // =================== PHASE A: sampling for gaussians [4b, 4b+4) ==========
    {
        float4* cA = (float4*)(sm + PA_CA);
        float4* cB = (float4*)(sm + PA_CB);
        int* s_wcnt  = (int*)(sm + PA_MISC);
        int* s_wbase = (int*)(sm + PA_MISC + 8);
        int* s_total = (int*)(sm + PA_MISC + 16);
        float* pus = sm + PA_PUS;
        float* ppd = sm + PA_PPD;

        if (tid == 0) *s_total = 0;
        __syncthreads();

        // tight bbox over this block's 4 gaussians
        const int i0 = b * 4;
        float bminx = 1e30f, bmaxx = -1e30f, bminy = 1e30f, bmaxy = -1e30f;
        #pragma unroll
        for (int g = 0; g < 4; ++g) {
            float mx = means[2 * (i0 + g)], my = means[2 * (i0 + g) + 1];
            bminx = fminf(bminx, mx); bmaxx = fmaxf(bmaxx, mx);
            bminy = fminf(bminy, my); bmaxy = fmaxf(bmaxy, my);
        }
        bminx -= 2.0f * DXC; bmaxx += 2.0f * DXC;
        bminy -= 2.0f * DXC; bmaxy += 2.0f * DXC;

        // candidate scan (4 rounds of 256), deterministic compaction
        const int wid = tid >> 5, lane = tid & 31;
        for (int c = 0; c < N_G / 256; ++c) {
            int j = c * 256 + tid;
            float mx = means[2 * j], my = means[2 * j + 1];
            float s0 = scaling[2 * j], s1 = scaling[2 * j + 1], t = transform[j];
            float A = s0 * s0, B = s0 * t, C = t * t + s1 * s1;
            float inv = 1.0f / (A * C - B * B);
            float ca =  C * inv, cb = -B * inv, cc = A * inv;
            float h = 0.5f * (A + C);
            float r = sqrtf(0.25f * (A - C) * (A - C) + B * B);
            float r2max = QCUT * (h + r);
            float ddx = fmaxf(fmaxf(bminx - mx, mx - bmaxx), 0.0f);
            float ddy = fmaxf(fmaxf(bminy - my, my - bmaxy), 0.0f);
            bool pred = (ddx * ddx + ddy * ddy) <= r2max;
            unsigned bm = __ballot_sync(0xffffffffu, pred);
            if (lane == 0) s_wcnt[wid] = __popc(bm);
            __syncthreads();
            if (tid == 0) {
                int acc = *s_total;
                for (int w2 = 0; w2 < 8; ++w2) { s_wbase[w2] = acc; acc += s_wcnt[w2]; }
                *s_total = acc;
            }
            __syncthreads();
            if (pred) {
                int idx = s_wbase[wid] + __popc(bm & ((1u << lane) - 1u));
                if (idx < CANDCAP) {
                    cA[idx] = make_float4(mx, my, r2max, u[j]);
                    cB[idx] = make_float4(ca, cb, cc, ca + cc);
                }
            }
            __syncthreads();
        }
        int cnt = *s_total;
        if (cnt > CANDCAP) cnt = CANDCAP;

        // evaluate 100 samples on 200 threads (2 threads/sample, even/odd split)
        float us = 0.0f, pd = 0.0f;
        float sx = 0.0f, sy = 0.0f;
        int   sl = 0;
        if (tid < 200) {
            int half = tid / 100;
            sl = tid - half * 100;
            const int s  = b * 100 + sl;
            const int i  = s / 25;
            const int k  = s % 25;
            const int kx = k / 5, ky = k % 5;
            sx = means[2 * i]     + (float)(kx - 2) * DXC;
            sy = means[2 * i + 1] + (float)(ky - 2) * DXC;
            for (int t2 = half; t2 < cnt; t2 += 2) {
                float4 A  = cA[t2];
                float4 Bv = cB[t2];
                float dx = sx - A.x;
                float dy = sy - A.y;
                float Cd0 = Bv.x * dx + Bv.y * dy;
                float Cd1 = Bv.y * dx + Bv.z * dy;
                float q   = dx * Cd0 + dy * Cd1;
                float w   = __expf(-0.5f * q) * A.w;
                us += w;
                pd += w * (Cd0 * Cd0 + Cd1 * Cd1 - Bv.w);
            }
            if (half == 1) { pus[sl] = us; ppd[sl] = pd; }
        }
        __syncthreads();
        if (tid < 100) {
            us += pus[sl];
            pd += ppd[sl];
            const int s = b * 100 + sl;
            const int i = s / 25;
            const int k = s % 25;
            float maskv = (fabsf(sx) < SCALE && fabsf(sy) < SCALE) ? 1.0f : 0.0f;
            d_img[i * 75 +  0 + k] = us;
            d_img[i * 75 + 25 + k] = pd;
            d_img[i * 75 + 50 + k] = maskv;
        }
    }

    // =================== GRID BARRIER (co-residency guaranteed) ==============
    __threadfence();
    __syncthreads();
    if (tid == 0) {
        atomicAdd(&g_arrive, 1u);
        while (atomicAdd(&g_arrive, 0u) < GRID_TOTAL) { }
    }
    __syncthreads();

    // =================== PHASE B: the 4 networks =============================
    float* swc  = sm + OFF_SWC;
    float* swe  = sm + OFF_SWE;
    float* swl  = sm + OFF_SWL;
    float* sbc  = sm + OFF_SBC;
    float* sbe  = sm + OFF_SBE;
    float* sbl  = sm + OFF_SBL;
    float* shw  = sm + OFF_SHW;
    float* shb  = sm + OFF_SHB;
    float* sprm = sm + OFF_SPRM;
    float* imgT = sm + OFF_IMGT;
    float* shT  = sm + OFF_SHT;
    float* sh2T = sm + OFF_SH2T;
    float* pp   = sm + OFF_PP;
    float* pp2  = sm + OFF_PP2;
    float* hpart= sm + OFF_HP;

    for (int idx = tid; idx < GPB * 75; idx += 256) {
        int g = idx / 75, kk = idx - g * 75;
        imgT[kk * 16 + g] = d_img[(g0 + g) * 75 + kk];
    }
    __syncthreads();

    // ---- stage 1: conv on 200 threads (1o x 4g) + emb on threads 200..255 ----
    if (tid < 200) {
        int o  = tid >> 2;              // 0..49
        int gb = (tid & 3) * 4;
        float acc[4];
        float b0 = sbc[o];
        acc[0] = b0; acc[1] = b0; acc[2] = b0; acc[3] = b0;
        const float* wr = &swc[o * 75];
        #pragma unroll 5
        for (int kk = 0; kk < 75; ++kk) {
            float w = wr[kk];
            float4 v = *(const float4*)&imgT[kk * 16 + gb];
            acc[0] = fmaf(w, v.x, acc[0]); acc[1] = fmaf(w, v.y, acc[1]);
            acc[2] = fmaf(w, v.z, acc[2]); acc[3] = fmaf(w, v.w, acc[3]);
        }
        #pragma unroll
        for (int bb = 0; bb < 4; ++bb) shT[o * 16 + gb + bb] = tanha(acc[bb]);
    } else {
        int et = tid - 200;             // 0..55
        for (int task = et; task < 120; task += 56) {
            int q  = task >> 2;         // 0..29
            int gb = (task & 3) * 4;
            float be = sbe[q];
            float acc[4] = {be, be, be, be};
            #pragma unroll
            for (int p = 0; p < 6; ++p) {
                float w = swe[p * 30 + q];
                acc[0] = fmaf(sprm[(gb + 0) * 9 + p], w, acc[0]);
                acc[1] = fmaf(sprm[(gb + 1) * 9 + p], w, acc[1]);
                acc[2] = fmaf(sprm[(gb + 2) * 9 + p], w, acc[2]);
                acc[3] = fmaf(sprm[(gb + 3) * 9 + p], w, acc[3]);
            }
            #pragma unroll
            for (int bb = 0; bb < 4; ++bb) shT[(50 + q) * 16 + gb + bb] = tanha(acc[bb]);
        }
    }
    __syncthreads();

    // ---- stage 2: 80x80 as 4q x 4g tiles, 3-way p split (240 threads) ----
    {
        const bool active = (tid < 240);
        int chunk = 0, q0 = 0, gb = 0, pst = 0, pen = 0;
        float acc[4][4];
        #pragma unroll
        for (int a = 0; a < 4; ++a)
            #pragma unroll
            for (int bb = 0; bb < 4; ++bb) acc[a][bb] = 0.0f;
        if (active) {
            chunk = tid / 80;            // 0,1,2
            int r = tid - chunk * 80;    // 0..79
            q0  = (r >> 2) * 4;          // 0..76
            gb  = (r & 3) * 4;           // 0,4,8,12
            pst = chunk * 27;
            pen = (chunk == 2) ? 80 : pst + 27;
            #pragma unroll 3
            for (int p = pst; p < pen; ++p) {
                float4 wv = *(const float4*)&swl[p * 80 + q0];
                float4 hv = *(const float4*)&shT[p * 16 + gb];
                acc[0][0] = fmaf(wv.x, hv.x, acc[0][0]); acc[0][1] = fmaf(wv.x, hv.y, acc[0][1]);
                acc[0][2] = fmaf(wv.x, hv.z, acc[0][2]); acc[0][3] = fmaf(wv.x, hv.w, acc[0][3]);
                acc[1][0] = fmaf(wv.y, hv.x, acc[1][0]); acc[1][1] = fmaf(wv.y, hv.y, acc[1][1]);
                acc[1][2] = fmaf(wv.y, hv.z, acc[1][2]); acc[1][3] = fmaf(wv.y, hv.w, acc[1][3]);
                acc[2][0] = fmaf(wv.z, hv.x, acc[2][0]); acc[2][1] = fmaf(wv.z, hv.y, acc[2][1]);
                acc[2][2] = fmaf(wv.z, hv.z, acc[2][2]); acc[2][3] = fmaf(wv.z, hv.w, acc[2][3]);
                acc[3][0] = fmaf(wv.w, hv.x, acc[3][0]); acc[3][1] = fmaf(wv.w, hv.y, acc[3][1]);
                acc[3][2] = fmaf(wv.w, hv.z, acc[3][2]); acc[3][3] = fmaf(wv.w, hv.w, acc[3][3]);
            }
        }
        if (active && chunk == 0) {
            #pragma unroll
            for (int a = 0; a < 4; ++a)
                #pragma unroll
                for (int bb = 0; bb < 4; ++bb)
                    pp[(q0 + a) * 16 + gb + bb] = acc[a][bb];
        }
        if (active && chunk == 1) {
            #pragma unroll
            for (int a = 0; a < 4; ++a)
                #pragma unroll
                for (int bb = 0; bb < 4; ++bb)
                    pp2[(q0 + a) * 16 + gb + bb] = acc[a][bb];
        }
        __syncthreads();                  // block-wide
        if (active && chunk == 2) {
            #pragma unroll
            for (int a = 0; a < 4; ++a) {
                float bl = sbl[q0 + a];
                #pragma unroll
                for (int bb = 0; bb < 4; ++bb)
                    sh2T[(q0 + a) * 16 + gb + bb] =
                        tanha(bl + acc[a][bb] + pp[(q0 + a) * 16 + gb + bb]
                                              + pp2[(q0 + a) * 16 + gb + bb]);
            }
        }
    }
    __syncthreads();

    // ---- stage 3: head, parallel over 4 p-chunks of 20 ----
    if (tid < od * 64) {
        int g = tid & 15;
        int r = tid >> 4;
        int d = r % od;
        int chunk = r / od;             // 0..3
        int pbase = chunk * 20;
        float acc = 0.0f;
        #pragma unroll 5
        for (int p = 0; p < 20; ++p)
            acc = fmaf(sh2T[(pbase + p) * 16 + g], shw[(pbase + p) * od + d], acc);
        hpart[(chunk * od + d) * 16 + g] = acc;
    }
    __syncthreads();
    if (tid < od * 16) {
        int g = tid & 15;
        int d = tid >> 4;
        float acc = shb[d];
        #pragma unroll
        for (int c = 0; c < 4; ++c) acc += hpart[(c * od + d) * 16 + g];
        int i = g0 + g;
        if      (m == 0) out[i * 6 + 0]     = sprm[g * 9 + 2]     + acc;
        else if (m == 1) out[i * 6 + 1 + d] = sprm[g * 9 + d]     + acc;
        else if (m == 2) out[i * 6 + 3 + d] = sprm[g * 9 + 3 + d] * __expf(acc);
        else             out[i * 6 + 5]     = sprm[g * 9 + 5]     + acc;
    }

    // ---- barrier counter reset (last block out restores initial state) ----
    __syncthreads();
    if (tid == 0) {
        unsigned d = atomicAdd(&g_depart, 1u) + 1u;
        if (d == GRID_TOTAL) { g_arrive = 0u; g_depart = 0u; __threadfence(); }
    }
}

// ---------------------------------------------------------------------------
extern "C" void kernel_launch(void* const* d_in, const int* in_sizes, int n_in,
                              void* d_out, int out_size)
{
    const float* means     = (const float*)d_in[0];
    const float* u         = (const float*)d_in[1];
    const float* scaling   = (const float*)d_in[2];
    const float* transform = (const float*)d_in[3];
    const float* conv_w    = (const float*)d_in[4];
    const float* conv_b    = (const float*)d_in[5];
    const float* emb_w     = (const float*)d_in[6];
    const float* emb_b     = (const float*)d_in[7];
    const float* lin1_w    = (const float*)d_in[8];
    const float* lin1_b    = (const float*)d_in[9];
    const float* sol_w     = (const float*)d_in[10];
    const float* sol_b     = (const float*)d_in[11];
    const float* tr_w      = (const float*)d_in[12];
    const float* tr_b      = (const float*)d_in[13];
    const float* sc_w      = (const float*)d_in[14];
    const float* sc_b      = (const float*)d_in[15];
    const float* tf_w      = (const float*)d_in[16];
    const float* tf_b      = (const float*)d_in[17];
    float* out             = (float*)d_out;

    static int smem_set = 0;
    if (!smem_set) {
        cudaFuncSetAttribute(k_all, cudaFuncAttributeMaxDynamicSharedMemorySize,
                             SMEM_FLTS * (int)sizeof(float));
        smem_set = 1;
    }

    k_all<<<GRID_TOTAL, 256, SMEM_FLTS * sizeof(float)>>>(
        means, u, scaling, transform,
        conv_w, conv_b, emb_w, emb_b, lin1_w, lin1_b,
        sol_w, sol_b, tr_w, tr_b, sc_w, sc_b, tf_w, tf_b, out);
}